// round 6
// baseline (speedup 1.0000x reference)
#include <cuda_runtime.h>
#include <cstdint>

#define N_NODES 50000
#define N_EDGES 625000
#define D       128
#define CAP     64          // bucket capacity per node (max degree ~45 expected)

// ---- scratch (__device__ globals; allocation-free requirement) ----
__device__ int2  g_bucket[N_NODES * CAP];   // 25.6 MB: (src, 1-d) per edge slot
__device__ int   g_cnt[N_NODES];            // in-degree / fill cursor
__device__ float g_xhi[N_NODES * D];        // tf32-truncated high part of x
__device__ float g_xlo[N_NODES * D];        // tf32-truncated residual of x
__device__ float g_wthi[D * D];             // Wt hi: [k][n]
__device__ float g_wtlo[D * D];             // Wt lo: [k][n]

// tf32 split by mantissa truncation (no special instructions)
__device__ __forceinline__ float tf32_trunc(float x) {
    return __uint_as_float(__float_as_uint(x) & 0xFFFFE000u);
}

// ---------------------------------------------------------------------------
// 1) prep: zero cnt + transpose/split W
// ---------------------------------------------------------------------------
__global__ void prep_kernel(const float* __restrict__ W) {
    int i = blockIdx.x * blockDim.x + threadIdx.x;
    int stride = gridDim.x * blockDim.x;
    for (int idx = i; idx < N_NODES; idx += stride) g_cnt[idx] = 0;
    for (int idx = i; idx < D * D; idx += stride) {
        int n = idx / D, k = idx % D;        // W row-major [n][k]
        float w = W[idx];
        float hi = tf32_trunc(w);
        g_wthi[k * D + n] = hi;
        g_wtlo[k * D + n] = tf32_trunc(w - hi);
    }
}

// ---------------------------------------------------------------------------
// 2) fill buckets: one thread per edge
// ---------------------------------------------------------------------------
__global__ void __launch_bounds__(256) fill_kernel(
    const float* __restrict__ d, const int* __restrict__ src,
    const int* __restrict__ dst)
{
    int e = blockIdx.x * blockDim.x + threadIdx.x;
    if (e >= N_EDGES) return;
    int t = __ldg(&dst[e]);
    int p = atomicAdd(&g_cnt[t], 1);
    if (p < CAP)
        g_bucket[t * CAP + p] = make_int2(__ldg(&src[e]), __float_as_int(1.0f - __ldg(&d[e])));
}

// ---------------------------------------------------------------------------
// 3) gather: one warp per node; x[v] = sum w_e h[src_e] + max(deg,1) h[v]
//    writes tf32 hi/lo split of x
// ---------------------------------------------------------------------------
__global__ void __launch_bounds__(256) gather_kernel(const float* __restrict__ h) {
    int v = blockIdx.x * (blockDim.x >> 5) + (threadIdx.x >> 5);
    if (v >= N_NODES) return;
    int lane = threadIdx.x & 31;

    int deg = g_cnt[v];
    int cap = min(deg, CAP);
    const float4* h4 = reinterpret_cast<const float4*>(h);
    float4 acc = make_float4(0.f, 0.f, 0.f, 0.f);

    for (int base = 0; base < cap; base += 32) {
        int idx = base + lane;
        int2 ent = make_int2(0, 0);
        if (idx < cap) ent = __ldg(&g_bucket[v * CAP + idx]);
        int cnt = min(32, cap - base);
        #pragma unroll 4
        for (int j = 0; j < cnt; j++) {
            int   sj = __shfl_sync(0xffffffffu, ent.x, j);
            float wj = __int_as_float(__shfl_sync(0xffffffffu, ent.y, j));
            float4 hv = __ldg(&h4[(size_t)sj * 32 + lane]);
            acc.x = fmaf(wj, hv.x, acc.x);
            acc.y = fmaf(wj, hv.y, acc.y);
            acc.z = fmaf(wj, hv.z, acc.z);
            acc.w = fmaf(wj, hv.w, acc.w);
        }
    }

    float degf = fmaxf((float)deg, 1.0f);
    float4 hv = __ldg(&h4[(size_t)v * 32 + lane]);
    float4 xv;
    xv.x = fmaf(degf, hv.x, acc.x);
    xv.y = fmaf(degf, hv.y, acc.y);
    xv.z = fmaf(degf, hv.z, acc.z);
    xv.w = fmaf(degf, hv.w, acc.w);

    float4 hi4, lo4;
    hi4.x = tf32_trunc(xv.x); lo4.x = tf32_trunc(xv.x - hi4.x);
    hi4.y = tf32_trunc(xv.y); lo4.y = tf32_trunc(xv.y - hi4.y);
    hi4.z = tf32_trunc(xv.z); lo4.z = tf32_trunc(xv.z - hi4.z);
    hi4.w = tf32_trunc(xv.w); lo4.w = tf32_trunc(xv.w - hi4.w);
    reinterpret_cast<float4*>(g_xhi)[(size_t)v * 32 + lane] = hi4;
    reinterpret_cast<float4*>(g_xlo)[(size_t)v * 32 + lane] = lo4;
}

// ---------------------------------------------------------------------------
// 4) GEMM + bias + ReLU via raw mma.sync tf32 (3-term split)
//    out = relu(x @ Wt + b)
//    256 thr / 8 warps; block tile 128M x 128N; warp tile 32M x 64N; BK=16.
// ---------------------------------------------------------------------------
#define XS_LD 20      // 16 + 4 pad
#define WS_LD 136     // 128 + 8 pad -> B-frag loads conflict-free

__device__ __forceinline__ void mma_tf32(
    float& c0, float& c1, float& c2, float& c3,
    unsigned a0, unsigned a1, unsigned a2, unsigned a3,
    unsigned b0, unsigned b1)
{
    asm volatile(
        "mma.sync.aligned.m16n8k8.row.col.f32.tf32.tf32.f32 "
        "{%0,%1,%2,%3}, {%4,%5,%6,%7}, {%8,%9}, {%0,%1,%2,%3};"
        : "+f"(c0), "+f"(c1), "+f"(c2), "+f"(c3)
        : "r"(a0), "r"(a1), "r"(a2), "r"(a3), "r"(b0), "r"(b1));
}

__global__ void __launch_bounds__(256) gemm_relu_kernel(
    const float* __restrict__ b, float* __restrict__ out)
{
    __shared__ float Xhi[128 * XS_LD];
    __shared__ float Xlo[128 * XS_LD];
    __shared__ float Whi[16 * WS_LD];
    __shared__ float Wlo[16 * WS_LD];

    const int tid  = threadIdx.x;
    const int wid  = tid >> 5;
    const int lane = tid & 31;
    const int warpM = wid & 3;           // 0..3 -> M offset warpM*32
    const int warpN = wid >> 2;          // 0..1 -> N offset warpN*64
    const int row0 = blockIdx.x * 128;

    const int qr = lane >> 2;            // 0..7
    const int qc = lane & 3;             // 0..3

    // accumulators [mi][nj][4], init with bias
    float acc[2][8][4];
    #pragma unroll
    for (int nj = 0; nj < 8; nj++) {
        int col = warpN * 64 + nj * 8 + qc * 2;
        float b0 = __ldg(&b[col]);
        float b1 = __ldg(&b[col + 1]);
        #pragma unroll
        for (int mi = 0; mi < 2; mi++) {
            acc[mi][nj][0] = b0; acc[mi][nj][1] = b1;
            acc[mi][nj][2] = b0; acc[mi][nj][3] = b1;
        }
    }

    // staging coords
    const int xm = tid >> 1;             // 0..127
    const int xc = (tid & 1) * 8;        // 0 or 8
    const int grow = row0 + xm;
    const bool rowok = grow < N_NODES;
    const int wr = tid >> 4;             // 0..15
    const int wc = (tid & 15) * 8;       // 0..120

    for (int kc = 0; kc < D; kc += 16) {
        // stage X hi/lo (128 x 16)
        #pragma unroll
        for (int q = 0; q < 2; q++) {
            float4 vh = make_float4(0.f, 0.f, 0.f, 0.f), vl = vh;
            if (rowok) {
                vh = *reinterpret_cast<const float4*>(&g_xhi[(size_t)grow * D + kc + xc + q * 4]);
                vl = *reinterpret_cast<const float4*>(&g_xlo[(size_t)grow * D + kc + xc + q * 4]);
            }
            *reinterpret_cast<float4*>(&Xhi[xm * XS_LD + xc + q * 4]) = vh;
            *reinterpret_cast<float4*>(&Xlo[xm * XS_LD + xc + q * 4]) = vl;
        }
        // stage W hi/lo (16 x 128)
        #pragma unroll
        for (int q = 0; q < 2; q++) {
            *reinterpret_cast<float4*>(&Whi[wr * WS_LD + wc + q * 4]) =
                *reinterpret_cast<const float4*>(&g_wthi[(kc + wr) * D + wc + q * 4]);
            *reinterpret_cast<float4*>(&Wlo[wr * WS_LD + wc + q * 4]) =
                *reinterpret_cast<const float4*>(&g_wtlo[(kc + wr) * D + wc + q * 4]);
        }
        __syncthreads();

        #pragma unroll
        for (int ks = 0; ks < 2; ks++) {
            const int k0 = ks * 8;
            // A fragments (hi & lo) for both 16-row tiles
            unsigned ahi[2][4], alo[2][4];
            #pragma unroll
            for (int mi = 0; mi < 2; mi++) {
                int r = warpM * 32 + mi * 16 + qr;
                ahi[mi][0] = __float_as_uint(Xhi[r * XS_LD + k0 + qc]);
                ahi[mi][1] = __float_as_uint(Xhi[(r + 8) * XS_LD + k0 + qc]);
                ahi[mi][2] = __float_as_uint(Xhi[r * XS_LD + k0 + qc + 4]);
                ahi[mi][3] = __float_as_uint(Xhi[(r + 8) * XS_LD + k0 + qc + 4]);
                alo[mi][0] = __float_as_uint(Xlo[r * XS_LD + k0 + qc]);
                alo[mi][1] = __float_as_uint(Xlo[(r + 8) * XS_LD + k0 + qc]);
                alo[mi][2] = __float_as_uint(Xlo[r * XS_LD + k0 + qc + 4]);
                alo[mi][3] = __float_as_uint(Xlo[(r + 8) * XS_LD + k0 + qc + 4]);
            }
            #pragma unroll
            for (int nj = 0; nj < 8; nj++) {
                int n = warpN * 64 + nj * 8 + qr;
                unsigned bh0 = __float_as_uint(Whi[(k0 + qc) * WS_LD + n]);
                unsigned bh1 = __float_as_uint(Whi[(k0 + qc + 4) * WS_LD + n]);
                unsigned bl0 = __float_as_uint(Wlo[(k0 + qc) * WS_LD + n]);
                unsigned bl1 = __float_as_uint(Wlo[(k0 + qc + 4) * WS_LD + n]);
                #pragma unroll
                for (int mi = 0; mi < 2; mi++) {
                    mma_tf32(acc[mi][nj][0], acc[mi][nj][1], acc[mi][nj][2], acc[mi][nj][3],
                             ahi[mi][0], ahi[mi][1], ahi[mi][2], ahi[mi][3], bh0, bh1);
                    mma_tf32(acc[mi][nj][0], acc[mi][nj][1], acc[mi][nj][2], acc[mi][nj][3],
                             ahi[mi][0], ahi[mi][1], ahi[mi][2], ahi[mi][3], bl0, bl1);
                    mma_tf32(acc[mi][nj][0], acc[mi][nj][1], acc[mi][nj][2], acc[mi][nj][3],
                             alo[mi][0], alo[mi][1], alo[mi][2], alo[mi][3], bh0, bh1);
                }
            }
        }
        __syncthreads();
    }

    // epilogue: relu + store (float2 per row-pair fragment)
    #pragma unroll
    for (int mi = 0; mi < 2; mi++) {
        int rA = row0 + warpM * 32 + mi * 16 + qr;
        int rB = rA + 8;
        #pragma unroll
        for (int nj = 0; nj < 8; nj++) {
            int col = warpN * 64 + nj * 8 + qc * 2;
            if (rA < N_NODES) {
                float2 o;
                o.x = fmaxf(acc[mi][nj][0], 0.f);
                o.y = fmaxf(acc[mi][nj][1], 0.f);
                *reinterpret_cast<float2*>(&out[(size_t)rA * D + col]) = o;
            }
            if (rB < N_NODES) {
                float2 o;
                o.x = fmaxf(acc[mi][nj][2], 0.f);
                o.y = fmaxf(acc[mi][nj][3], 0.f);
                *reinterpret_cast<float2*>(&out[(size_t)rB * D + col]) = o;
            }
        }
    }
}

// ---------------------------------------------------------------------------
extern "C" void kernel_launch(void* const* d_in, const int* in_sizes, int n_in,
                              void* d_out, int out_size)
{
    const float* h   = (const float*)d_in[0];
    const float* d   = (const float*)d_in[1];
    const int*   src = (const int*)d_in[2];
    const int*   dst = (const int*)d_in[3];
    const float* W   = (const float*)d_in[4];
    const float* b   = (const float*)d_in[5];
    float* out = (float*)d_out;

    prep_kernel<<<256, 256>>>(W);
    fill_kernel<<<(N_EDGES + 255) / 256, 256>>>(d, src, dst);
    gather_kernel<<<(N_NODES + 7) / 8, 256>>>(h);
    gemm_relu_kernel<<<(N_NODES + 127) / 128, 256>>>(b, out);
}

// round 7
// speedup vs baseline: 1.3780x; 1.3780x over previous
#include <cuda_runtime.h>
#include <cuda_bf16.h>
#include <cstdint>

#define N_NODES 50000
#define N_EDGES 625000
#define D       128
#define CAP     64          // bucket capacity per node (max degree ~45 expected)

// ---- scratch (__device__ globals; allocation-free requirement) ----
__device__ int2           g_bucket[N_NODES * CAP]; // 25.6 MB
__device__ int            g_cnt[N_NODES];
__device__ __nv_bfloat16  g_xhi[N_NODES * D];      // bf16 high part of x
__device__ __nv_bfloat16  g_xlo[N_NODES * D];      // bf16 residual of x
__device__ __nv_bfloat16  g_wthi[D * D];           // Wt hi: [k][n]
__device__ __nv_bfloat16  g_wtlo[D * D];           // Wt lo: [k][n]

__device__ __forceinline__ unsigned pack2(__nv_bfloat16 a, __nv_bfloat16 b) {
    __nv_bfloat162 t = __halves2bfloat162(a, b);
    return *reinterpret_cast<unsigned*>(&t);
}

// ---------------------------------------------------------------------------
// 1) prep: zero cnt + transpose/split W into bf16 hi/lo
// ---------------------------------------------------------------------------
__global__ void prep_kernel(const float* __restrict__ W) {
    int i = blockIdx.x * blockDim.x + threadIdx.x;
    int stride = gridDim.x * blockDim.x;
    for (int idx = i; idx < N_NODES; idx += stride) g_cnt[idx] = 0;
    for (int idx = i; idx < D * D; idx += stride) {
        int n = idx / D, k = idx % D;        // W row-major [n][k]
        float w = W[idx];
        __nv_bfloat16 hi = __float2bfloat16(w);
        __nv_bfloat16 lo = __float2bfloat16(w - __bfloat162float(hi));
        g_wthi[k * D + n] = hi;
        g_wtlo[k * D + n] = lo;
    }
}

// ---------------------------------------------------------------------------
// 2) fill buckets: one thread per edge
// ---------------------------------------------------------------------------
__global__ void __launch_bounds__(256) fill_kernel(
    const float* __restrict__ d, const int* __restrict__ src,
    const int* __restrict__ dst)
{
    int e = blockIdx.x * blockDim.x + threadIdx.x;
    if (e >= N_EDGES) return;
    int t = __ldg(&dst[e]);
    int p = atomicAdd(&g_cnt[t], 1);
    if (p < CAP)
        g_bucket[t * CAP + p] = make_int2(__ldg(&src[e]), __float_as_int(1.0f - __ldg(&d[e])));
}

// ---------------------------------------------------------------------------
// 3) gather: one warp per node; x[v] = sum w_e h[src_e] + max(deg,1) h[v]
//    fp32 accumulate, bf16 hi/lo split on output
// ---------------------------------------------------------------------------
__global__ void __launch_bounds__(256) gather_kernel(const float* __restrict__ h) {
    int v = blockIdx.x * (blockDim.x >> 5) + (threadIdx.x >> 5);
    if (v >= N_NODES) return;
    int lane = threadIdx.x & 31;

    int deg = g_cnt[v];
    int cap = min(deg, CAP);
    const float4* h4 = reinterpret_cast<const float4*>(h);
    float4 acc = make_float4(0.f, 0.f, 0.f, 0.f);

    for (int base = 0; base < cap; base += 32) {
        int idx = base + lane;
        int2 ent = make_int2(0, 0);
        if (idx < cap) ent = __ldg(&g_bucket[v * CAP + idx]);
        int cnt = min(32, cap - base);
        #pragma unroll 4
        for (int j = 0; j < cnt; j++) {
            int   sj = __shfl_sync(0xffffffffu, ent.x, j);
            float wj = __int_as_float(__shfl_sync(0xffffffffu, ent.y, j));
            float4 hv = __ldg(&h4[(size_t)sj * 32 + lane]);
            acc.x = fmaf(wj, hv.x, acc.x);
            acc.y = fmaf(wj, hv.y, acc.y);
            acc.z = fmaf(wj, hv.z, acc.z);
            acc.w = fmaf(wj, hv.w, acc.w);
        }
    }

    float degf = fmaxf((float)deg, 1.0f);
    float4 hv = __ldg(&h4[(size_t)v * 32 + lane]);
    float x0 = fmaf(degf, hv.x, acc.x);
    float x1 = fmaf(degf, hv.y, acc.y);
    float x2 = fmaf(degf, hv.z, acc.z);
    float x3 = fmaf(degf, hv.w, acc.w);

    __nv_bfloat16 h0 = __float2bfloat16(x0), h1 = __float2bfloat16(x1);
    __nv_bfloat16 h2 = __float2bfloat16(x2), h3 = __float2bfloat16(x3);
    __nv_bfloat16 l0 = __float2bfloat16(x0 - __bfloat162float(h0));
    __nv_bfloat16 l1 = __float2bfloat16(x1 - __bfloat162float(h1));
    __nv_bfloat16 l2 = __float2bfloat16(x2 - __bfloat162float(h2));
    __nv_bfloat16 l3 = __float2bfloat16(x3 - __bfloat162float(h3));

    uint2 uh, ul;
    uh.x = pack2(h0, h1); uh.y = pack2(h2, h3);
    ul.x = pack2(l0, l1); ul.y = pack2(l2, l3);
    *reinterpret_cast<uint2*>(&g_xhi[(size_t)v * D + lane * 4]) = uh;
    *reinterpret_cast<uint2*>(&g_xlo[(size_t)v * D + lane * 4]) = ul;
}

// ---------------------------------------------------------------------------
// 4) GEMM + bias + ReLU via mma.sync bf16 m16n8k16, 3-term hi/lo split
//    out = relu(x @ Wt + b)
//    256 thr / 8 warps; block tile 128M x 128N; warp 32M x 64N; BK=32.
// ---------------------------------------------------------------------------
#define XS_LD 40      // bf16 elements per X smem row (32 + 8 pad) -> ldmatrix conflict-free
#define WS_LD 136     // bf16 elements per W smem row (128 + 8 pad) -> conflict-free

__device__ __forceinline__ void ldsm4(unsigned& r0, unsigned& r1, unsigned& r2, unsigned& r3,
                                      const __nv_bfloat16* p) {
    unsigned a = (unsigned)__cvta_generic_to_shared(p);
    asm volatile("ldmatrix.sync.aligned.m8n8.x4.shared.b16 {%0,%1,%2,%3}, [%4];"
                 : "=r"(r0), "=r"(r1), "=r"(r2), "=r"(r3) : "r"(a));
}
__device__ __forceinline__ void ldsm4t(unsigned& r0, unsigned& r1, unsigned& r2, unsigned& r3,
                                       const __nv_bfloat16* p) {
    unsigned a = (unsigned)__cvta_generic_to_shared(p);
    asm volatile("ldmatrix.sync.aligned.m8n8.x4.trans.shared.b16 {%0,%1,%2,%3}, [%4];"
                 : "=r"(r0), "=r"(r1), "=r"(r2), "=r"(r3) : "r"(a));
}
__device__ __forceinline__ void mma_bf16(
    float& c0, float& c1, float& c2, float& c3,
    unsigned a0, unsigned a1, unsigned a2, unsigned a3,
    unsigned b0, unsigned b1)
{
    asm volatile(
        "mma.sync.aligned.m16n8k16.row.col.f32.bf16.bf16.f32 "
        "{%0,%1,%2,%3}, {%4,%5,%6,%7}, {%8,%9}, {%0,%1,%2,%3};"
        : "+f"(c0), "+f"(c1), "+f"(c2), "+f"(c3)
        : "r"(a0), "r"(a1), "r"(a2), "r"(a3), "r"(b0), "r"(b1));
}

__global__ void __launch_bounds__(256, 2) gemm_relu_kernel(
    const float* __restrict__ b, float* __restrict__ out)
{
    __shared__ __nv_bfloat16 Xhi[128 * XS_LD];
    __shared__ __nv_bfloat16 Xlo[128 * XS_LD];
    __shared__ __nv_bfloat16 Whi[32 * WS_LD];
    __shared__ __nv_bfloat16 Wlo[32 * WS_LD];

    const int tid  = threadIdx.x;
    const int wid  = tid >> 5;
    const int lane = tid & 31;
    const int warpM = wid & 3;           // M offset warpM*32
    const int warpN = wid >> 2;          // N offset warpN*64
    const int row0 = blockIdx.x * 128;
    const int qr = lane >> 2;            // 0..7
    const int qc = lane & 3;             // 0..3

    // accumulators [mi][nj][4], init with bias
    float acc[2][8][4];
    #pragma unroll
    for (int nj = 0; nj < 8; nj++) {
        int col = warpN * 64 + nj * 8 + qc * 2;
        float b0 = __ldg(&b[col]);
        float b1 = __ldg(&b[col + 1]);
        #pragma unroll
        for (int mi = 0; mi < 2; mi++) {
            acc[mi][nj][0] = b0; acc[mi][nj][1] = b1;
            acc[mi][nj][2] = b0; acc[mi][nj][3] = b1;
        }
    }

    // staging coords
    const int xm = tid >> 1;             // 0..127 (row)
    const int xs = (tid & 1) * 16;       // 16-col segment
    const int grow = row0 + xm;
    const bool rowok = grow < N_NODES;
    const int wr = tid >> 3;             // 0..31 (k row)
    const int ws = (tid & 7) * 16;       // 16-col segment

    // ldmatrix lane addressing (same index math for A and B^T)
    const int lrow = (lane & 7) + ((lane >> 3) & 1) * 8;
    const int lk8  = (lane >> 4) * 8;

    for (int kc = 0; kc < D; kc += 32) {
        // stage X hi/lo (128 x 32 bf16): 2 x uint4 per thread per array
        uint4 z = make_uint4(0, 0, 0, 0);
        uint4 vh0 = z, vh1 = z, vl0 = z, vl1 = z;
        if (rowok) {
            const uint4* ph = reinterpret_cast<const uint4*>(&g_xhi[(size_t)grow * D + kc + xs]);
            const uint4* pl = reinterpret_cast<const uint4*>(&g_xlo[(size_t)grow * D + kc + xs]);
            vh0 = __ldg(&ph[0]); vh1 = __ldg(&ph[1]);
            vl0 = __ldg(&pl[0]); vl1 = __ldg(&pl[1]);
        }
        *reinterpret_cast<uint4*>(&Xhi[xm * XS_LD + xs])     = vh0;
        *reinterpret_cast<uint4*>(&Xhi[xm * XS_LD + xs + 8]) = vh1;
        *reinterpret_cast<uint4*>(&Xlo[xm * XS_LD + xs])     = vl0;
        *reinterpret_cast<uint4*>(&Xlo[xm * XS_LD + xs + 8]) = vl1;
        // stage W hi/lo (32 x 128 bf16)
        {
            const uint4* ph = reinterpret_cast<const uint4*>(&g_wthi[(kc + wr) * D + ws]);
            const uint4* pl = reinterpret_cast<const uint4*>(&g_wtlo[(kc + wr) * D + ws]);
            *reinterpret_cast<uint4*>(&Whi[wr * WS_LD + ws])     = __ldg(&ph[0]);
            *reinterpret_cast<uint4*>(&Whi[wr * WS_LD + ws + 8]) = __ldg(&ph[1]);
            *reinterpret_cast<uint4*>(&Wlo[wr * WS_LD + ws])     = __ldg(&pl[0]);
            *reinterpret_cast<uint4*>(&Wlo[wr * WS_LD + ws + 8]) = __ldg(&pl[1]);
        }
        __syncthreads();

        #pragma unroll
        for (int ks = 0; ks < 2; ks++) {
            const int k0 = ks * 16;
            // A fragments via ldmatrix.x4 (16x16 per mi)
            unsigned ahi[2][4], alo[2][4];
            #pragma unroll
            for (int mi = 0; mi < 2; mi++) {
                const __nv_bfloat16* pa = &Xhi[(warpM * 32 + mi * 16 + lrow) * XS_LD + k0 + lk8];
                ldsm4(ahi[mi][0], ahi[mi][1], ahi[mi][2], ahi[mi][3], pa);
                const __nv_bfloat16* pl = &Xlo[(warpM * 32 + mi * 16 + lrow) * XS_LD + k0 + lk8];
                ldsm4(alo[mi][0], alo[mi][1], alo[mi][2], alo[mi][3], pl);
            }
            // B fragments: ldmatrix.x4.trans covers 16k x 16n (two nj)
            #pragma unroll
            for (int njp = 0; njp < 4; njp++) {
                const int n0 = warpN * 64 + njp * 16;
                unsigned bh[4], bl[4];
                ldsm4t(bh[0], bh[1], bh[2], bh[3], &Whi[(k0 + lrow) * WS_LD + n0 + lk8]);
                ldsm4t(bl[0], bl[1], bl[2], bl[3], &Wlo[(k0 + lrow) * WS_LD + n0 + lk8]);
                const int nj0 = njp * 2, nj1 = njp * 2 + 1;
                #pragma unroll
                for (int mi = 0; mi < 2; mi++) {
                    mma_bf16(acc[mi][nj0][0], acc[mi][nj0][1], acc[mi][nj0][2], acc[mi][nj0][3],
                             ahi[mi][0], ahi[mi][1], ahi[mi][2], ahi[mi][3], bh[0], bh[1]);
                    mma_bf16(acc[mi][nj0][0], acc[mi][nj0][1], acc[mi][nj0][2], acc[mi][nj0][3],
                             ahi[mi][0], ahi[mi][1], ahi[mi][2], ahi[mi][3], bl[0], bl[1]);
                    mma_bf16(acc[mi][nj0][0], acc[mi][nj0][1], acc[mi][nj0][2], acc[mi][nj0][3],
                             alo[mi][0], alo[mi][1], alo[mi][2], alo[mi][3], bh[0], bh[1]);
                    mma_bf16(acc[mi][nj1][0], acc[mi][nj1][1], acc[mi][nj1][2], acc[mi][nj1][3],
                             ahi[mi][0], ahi[mi][1], ahi[mi][2], ahi[mi][3], bh[2], bh[3]);
                    mma_bf16(acc[mi][nj1][0], acc[mi][nj1][1], acc[mi][nj1][2], acc[mi][nj1][3],
                             ahi[mi][0], ahi[mi][1], ahi[mi][2], ahi[mi][3], bl[2], bl[3]);
                    mma_bf16(acc[mi][nj1][0], acc[mi][nj1][1], acc[mi][nj1][2], acc[mi][nj1][3],
                             alo[mi][0], alo[mi][1], alo[mi][2], alo[mi][3], bh[2], bh[3]);
                }
            }
        }
        __syncthreads();
    }

    // epilogue: relu + store
    #pragma unroll
    for (int mi = 0; mi < 2; mi++) {
        int rA = row0 + warpM * 32 + mi * 16 + qr;
        int rB = rA + 8;
        #pragma unroll
        for (int nj = 0; nj < 8; nj++) {
            int col = warpN * 64 + nj * 8 + qc * 2;
            if (rA < N_NODES) {
                float2 o;
                o.x = fmaxf(acc[mi][nj][0], 0.f);
                o.y = fmaxf(acc[mi][nj][1], 0.f);
                *reinterpret_cast<float2*>(&out[(size_t)rA * D + col]) = o;
            }
            if (rB < N_NODES) {
                float2 o;
                o.x = fmaxf(acc[mi][nj][2], 0.f);
                o.y = fmaxf(acc[mi][nj][3], 0.f);
                *reinterpret_cast<float2*>(&out[(size_t)rB * D + col]) = o;
            }
        }
    }
}

// ---------------------------------------------------------------------------
extern "C" void kernel_launch(void* const* d_in, const int* in_sizes, int n_in,
                              void* d_out, int out_size)
{
    const float* h   = (const float*)d_in[0];
    const float* d   = (const float*)d_in[1];
    const int*   src = (const int*)d_in[2];
    const int*   dst = (const int*)d_in[3];
    const float* W   = (const float*)d_in[4];
    const float* b   = (const float*)d_in[5];
    float* out = (float*)d_out;

    prep_kernel<<<256, 256>>>(W);
    fill_kernel<<<(N_EDGES + 255) / 256, 256>>>(d, src, dst);
    gather_kernel<<<(N_NODES + 7) / 8, 256>>>(h);
    gemm_relu_kernel<<<(N_NODES + 127) / 128, 256>>>(b, out);
}

// round 9
// speedup vs baseline: 1.4995x; 1.0882x over previous
#include <cuda_runtime.h>
#include <cuda_bf16.h>
#include <cstdint>

#define N_NODES 50000
#define N_EDGES 625000
#define D       128
#define CAP     64          // bucket capacity per node (max degree ~45 expected)

// ---- scratch (__device__ globals; allocation-free requirement) ----
__device__ int2           g_bucket[N_NODES * CAP]; // 25.6 MB
__device__ int            g_cnt[N_NODES];
__device__ __nv_bfloat16  g_xhi[N_NODES * D];      // bf16 high part of x
__device__ __nv_bfloat16  g_xlo[N_NODES * D];      // bf16 residual of x
__device__ __nv_bfloat16  g_wthi[D * D];           // Wt hi: [k][n]
__device__ __nv_bfloat16  g_wtlo[D * D];           // Wt lo: [k][n]

__device__ __forceinline__ unsigned pack2(__nv_bfloat16 a, __nv_bfloat16 b) {
    __nv_bfloat162 t = __halves2bfloat162(a, b);
    return *reinterpret_cast<unsigned*>(&t);
}

// ---------------------------------------------------------------------------
// 1) prep: zero cnt + transpose/split W into bf16 hi/lo
// ---------------------------------------------------------------------------
__global__ void prep_kernel(const float* __restrict__ W) {
    int i = blockIdx.x * blockDim.x + threadIdx.x;
    int stride = gridDim.x * blockDim.x;
    for (int idx = i; idx < N_NODES; idx += stride) g_cnt[idx] = 0;
    for (int idx = i; idx < D * D; idx += stride) {
        int n = idx / D, k = idx % D;        // W row-major [n][k]
        float w = W[idx];
        __nv_bfloat16 hi = __float2bfloat16(w);
        __nv_bfloat16 lo = __float2bfloat16(w - __bfloat162float(hi));
        g_wthi[k * D + n] = hi;
        g_wtlo[k * D + n] = lo;
    }
}

// ---------------------------------------------------------------------------
// 2) fill buckets: 4 edges per thread (vectorized index loads)
// ---------------------------------------------------------------------------
__global__ void __launch_bounds__(256) fill_kernel(
    const float* __restrict__ d, const int* __restrict__ src,
    const int* __restrict__ dst)
{
    int i = blockIdx.x * blockDim.x + threadIdx.x;
    if (i * 4 >= N_EDGES) return;
    int4   s4 = __ldg(reinterpret_cast<const int4*>(src) + i);
    int4   t4 = __ldg(reinterpret_cast<const int4*>(dst) + i);
    float4 d4 = __ldg(reinterpret_cast<const float4*>(d) + i);

    int p;
    p = atomicAdd(&g_cnt[t4.x], 1);
    if (p < CAP) g_bucket[t4.x * CAP + p] = make_int2(s4.x, __float_as_int(1.0f - d4.x));
    p = atomicAdd(&g_cnt[t4.y], 1);
    if (p < CAP) g_bucket[t4.y * CAP + p] = make_int2(s4.y, __float_as_int(1.0f - d4.y));
    p = atomicAdd(&g_cnt[t4.z], 1);
    if (p < CAP) g_bucket[t4.z * CAP + p] = make_int2(s4.z, __float_as_int(1.0f - d4.z));
    p = atomicAdd(&g_cnt[t4.w], 1);
    if (p < CAP) g_bucket[t4.w * CAP + p] = make_int2(s4.w, __float_as_int(1.0f - d4.w));
}

// ---------------------------------------------------------------------------
// 3) gather: one warp per node; x[v] = sum w_e h[src_e] + max(deg,1) h[v]
//    fp32 accumulate, bf16 hi/lo split on output
// ---------------------------------------------------------------------------
__global__ void __launch_bounds__(256) gather_kernel(const float* __restrict__ h) {
    int v = blockIdx.x * (blockDim.x >> 5) + (threadIdx.x >> 5);
    if (v >= N_NODES) return;
    int lane = threadIdx.x & 31;

    int deg = g_cnt[v];
    int cap = min(deg, CAP);
    const float4* h4 = reinterpret_cast<const float4*>(h);
    float4 acc = make_float4(0.f, 0.f, 0.f, 0.f);

    for (int base = 0; base < cap; base += 32) {
        int idx = base + lane;
        int2 ent = make_int2(0, 0);
        if (idx < cap) ent = __ldg(&g_bucket[v * CAP + idx]);
        int cnt = min(32, cap - base);
        #pragma unroll 4
        for (int j = 0; j < cnt; j++) {
            int   sj = __shfl_sync(0xffffffffu, ent.x, j);
            float wj = __int_as_float(__shfl_sync(0xffffffffu, ent.y, j));
            float4 hv = __ldg(&h4[(size_t)sj * 32 + lane]);
            acc.x = fmaf(wj, hv.x, acc.x);
            acc.y = fmaf(wj, hv.y, acc.y);
            acc.z = fmaf(wj, hv.z, acc.z);
            acc.w = fmaf(wj, hv.w, acc.w);
        }
    }

    float degf = fmaxf((float)deg, 1.0f);
    float4 hv = __ldg(&h4[(size_t)v * 32 + lane]);
    float x0 = fmaf(degf, hv.x, acc.x);
    float x1 = fmaf(degf, hv.y, acc.y);
    float x2 = fmaf(degf, hv.z, acc.z);
    float x3 = fmaf(degf, hv.w, acc.w);

    __nv_bfloat16 h0 = __float2bfloat16(x0), h1 = __float2bfloat16(x1);
    __nv_bfloat16 h2 = __float2bfloat16(x2), h3 = __float2bfloat16(x3);
    __nv_bfloat16 l0 = __float2bfloat16(x0 - __bfloat162float(h0));
    __nv_bfloat16 l1 = __float2bfloat16(x1 - __bfloat162float(h1));
    __nv_bfloat16 l2 = __float2bfloat16(x2 - __bfloat162float(h2));
    __nv_bfloat16 l3 = __float2bfloat16(x3 - __bfloat162float(h3));

    uint2 uh, ul;
    uh.x = pack2(h0, h1); uh.y = pack2(h2, h3);
    ul.x = pack2(l0, l1); ul.y = pack2(l2, l3);
    *reinterpret_cast<uint2*>(&g_xhi[(size_t)v * D + lane * 4]) = uh;
    *reinterpret_cast<uint2*>(&g_xlo[(size_t)v * D + lane * 4]) = ul;
}

// ---------------------------------------------------------------------------
// 4) GEMM + bias + ReLU via mma.sync bf16 m16n8k16 (3-term hi/lo split),
//    register double-buffered global loads. out = relu(x @ Wt + b)
//    256 thr / 8 warps; block tile 128M x 128N; warp 32M x 64N; BK=32 x 4.
// ---------------------------------------------------------------------------
#define XS_LD 40      // bf16/row: 32 + 8 pad -> ldmatrix conflict-free
#define WS_LD 136     // bf16/row: 128 + 8 pad -> conflict-free
#define NCHUNK (D / 32)

__device__ __forceinline__ void ldsm4(unsigned& r0, unsigned& r1, unsigned& r2, unsigned& r3,
                                      const __nv_bfloat16* p) {
    unsigned a = (unsigned)__cvta_generic_to_shared(p);
    asm volatile("ldmatrix.sync.aligned.m8n8.x4.shared.b16 {%0,%1,%2,%3}, [%4];"
                 : "=r"(r0), "=r"(r1), "=r"(r2), "=r"(r3) : "r"(a));
}
__device__ __forceinline__ void ldsm4t(unsigned& r0, unsigned& r1, unsigned& r2, unsigned& r3,
                                       const __nv_bfloat16* p) {
    unsigned a = (unsigned)__cvta_generic_to_shared(p);
    asm volatile("ldmatrix.sync.aligned.m8n8.x4.trans.shared.b16 {%0,%1,%2,%3}, [%4];"
                 : "=r"(r0), "=r"(r1), "=r"(r2), "=r"(r3) : "r"(a));
}
__device__ __forceinline__ void mma_bf16(
    float& c0, float& c1, float& c2, float& c3,
    unsigned a0, unsigned a1, unsigned a2, unsigned a3,
    unsigned b0, unsigned b1)
{
    asm volatile(
        "mma.sync.aligned.m16n8k16.row.col.f32.bf16.bf16.f32 "
        "{%0,%1,%2,%3}, {%4,%5,%6,%7}, {%8,%9}, {%0,%1,%2,%3};"
        : "+f"(c0), "+f"(c1), "+f"(c2), "+f"(c3)
        : "r"(a0), "r"(a1), "r"(a2), "r"(a3), "r"(b0), "r"(b1));
}

__global__ void __launch_bounds__(256, 2) gemm_relu_kernel(
    const float* __restrict__ b, float* __restrict__ out)
{
    __shared__ __nv_bfloat16 Xhi[128 * XS_LD];
    __shared__ __nv_bfloat16 Xlo[128 * XS_LD];
    __shared__ __nv_bfloat16 Whi[32 * WS_LD];
    __shared__ __nv_bfloat16 Wlo[32 * WS_LD];

    const int tid  = threadIdx.x;
    const int wid  = tid >> 5;
    const int lane = tid & 31;
    const int warpM = wid & 3;
    const int warpN = wid >> 2;
    const int row0 = blockIdx.x * 128;
    const int qr = lane >> 2;
    const int qc = lane & 3;

    float acc[2][8][4];
    #pragma unroll
    for (int nj = 0; nj < 8; nj++) {
        int col = warpN * 64 + nj * 8 + qc * 2;
        float b0 = __ldg(&b[col]);
        float b1 = __ldg(&b[col + 1]);
        #pragma unroll
        for (int mi = 0; mi < 2; mi++) {
            acc[mi][nj][0] = b0; acc[mi][nj][1] = b1;
            acc[mi][nj][2] = b0; acc[mi][nj][3] = b1;
        }
    }

    // staging coords: X 128x32 bf16 (64B/row), W 32x128 (256B/row)
    const int xm = tid >> 1;             // row 0..127
    const int xs = (tid & 1) * 16;       // 16-bf16 segment
    const int grow = row0 + xm;
    const bool rowok = grow < N_NODES;
    const int growc = rowok ? grow : 0;
    const int wr = tid >> 3;             // 0..31 (k row)
    const int ws = (tid & 7) * 16;       // 16-bf16 segment

    const int lrow = (lane & 7) + ((lane >> 3) & 1) * 8;
    const int lk8  = (lane >> 4) * 8;

    // prefetch registers (8 x uint4)
    uint4 pxh0, pxh1, pxl0, pxl1, pwh0, pwh1, pwl0, pwl1;
    const uint4 zz = make_uint4(0, 0, 0, 0);

#define LOAD_CHUNK(KC)                                                                     \
    do {                                                                                   \
        if (rowok) {                                                                       \
            const uint4* ph = reinterpret_cast<const uint4*>(&g_xhi[(size_t)growc * D + (KC) + xs]); \
            const uint4* pl = reinterpret_cast<const uint4*>(&g_xlo[(size_t)growc * D + (KC) + xs]); \
            pxh0 = __ldg(&ph[0]); pxh1 = __ldg(&ph[1]);                                    \
            pxl0 = __ldg(&pl[0]); pxl1 = __ldg(&pl[1]);                                    \
        } else { pxh0 = zz; pxh1 = zz; pxl0 = zz; pxl1 = zz; }                             \
        {                                                                                  \
            const uint4* ph = reinterpret_cast<const uint4*>(&g_wthi[((KC) + wr) * D + ws]); \
            const uint4* pl = reinterpret_cast<const uint4*>(&g_wtlo[((KC) + wr) * D + ws]); \
            pwh0 = __ldg(&ph[0]); pwh1 = __ldg(&ph[1]);                                    \
            pwl0 = __ldg(&pl[0]); pwl1 = __ldg(&pl[1]);                                    \
        }                                                                                  \
    } while (0)

#define STORE_CHUNK()                                                                      \
    do {                                                                                   \
        *reinterpret_cast<uint4*>(&Xhi[xm * XS_LD + xs])     = pxh0;                       \
        *reinterpret_cast<uint4*>(&Xhi[xm * XS_LD + xs + 8]) = pxh1;                       \
        *reinterpret_cast<uint4*>(&Xlo[xm * XS_LD + xs])     = pxl0;                       \
        *reinterpret_cast<uint4*>(&Xlo[xm * XS_LD + xs + 8]) = pxl1;                       \
        *reinterpret_cast<uint4*>(&Whi[wr * WS_LD + ws])     = pwh0;                       \
        *reinterpret_cast<uint4*>(&Whi[wr * WS_LD + ws + 8]) = pwh1;                       \
        *reinterpret_cast<uint4*>(&Wlo[wr * WS_LD + ws])     = pwl0;                       \
        *reinterpret_cast<uint4*>(&Wlo[wr * WS_LD + ws + 8]) = pwl1;                       \
    } while (0)

    LOAD_CHUNK(0);

    #pragma unroll
    for (int chunk = 0; chunk < NCHUNK; chunk++) {
        STORE_CHUNK();
        __syncthreads();
        // issue next chunk's global loads; latency overlaps the MMAs below
        if (chunk + 1 < NCHUNK) LOAD_CHUNK((chunk + 1) * 32);

        #pragma unroll
        for (int ks = 0; ks < 2; ks++) {
            const int k0 = ks * 16;
            unsigned ahi[2][4], alo[2][4];
            #pragma unroll
            for (int mi = 0; mi < 2; mi++) {
                ldsm4(ahi[mi][0], ahi[mi][1], ahi[mi][2], ahi[mi][3],
                      &Xhi[(warpM * 32 + mi * 16 + lrow) * XS_LD + k0 + lk8]);
                ldsm4(alo[mi][0], alo[mi][1], alo[mi][2], alo[mi][3],
                      &Xlo[(warpM * 32 + mi * 16 + lrow) * XS_LD + k0 + lk8]);
            }
            #pragma unroll
            for (int njp = 0; njp < 4; njp++) {
                const int n0 = warpN * 64 + njp * 16;
                unsigned bh[4], bl[4];
                ldsm4t(bh[0], bh[1], bh[2], bh[3], &Whi[(k0 + lrow) * WS_LD + n0 + lk8]);
                ldsm4t(bl[0], bl[1], bl[2], bl[3], &Wlo[(k0 + lrow) * WS_LD + n0 + lk8]);
                const int nj0 = njp * 2, nj1 = njp * 2 + 1;
                #pragma unroll
                for (int mi = 0; mi < 2; mi++) {
                    mma_bf16(acc[mi][nj0][0], acc[mi][nj0][1], acc[mi][nj0][2], acc[mi][nj0][3],
                             ahi[mi][0], ahi[mi][1], ahi[mi][2], ahi[mi][3], bh[0], bh[1]);
                    mma_bf16(acc[mi][nj0][0], acc[mi][nj0][1], acc[mi][nj0][2], acc[mi][nj0][3],
                             ahi[mi][0], ahi[mi][1], ahi[mi][2], ahi[mi][3], bl[0], bl[1]);
                    mma_bf16(acc[mi][nj0][0], acc[mi][nj0][1], acc[mi][nj0][2], acc[mi][nj0][3],
                             alo[mi][0], alo[mi][1], alo[mi][2], alo[mi][3], bh[0], bh[1]);
                    mma_bf16(acc[mi][nj1][0], acc[mi][nj1][1], acc[mi][nj1][2], acc[mi][nj1][3],
                             ahi[mi][0], ahi[mi][1], ahi[mi][2], ahi[mi][3], bh[2], bh[3]);
                    mma_bf16(acc[mi][nj1][0], acc[mi][nj1][1], acc[mi][nj1][2], acc[mi][nj1][3],
                             ahi[mi][0], ahi[mi][1], ahi[mi][2], ahi[mi][3], bl[2], bl[3]);
                    mma_bf16(acc[mi][nj1][0], acc[mi][nj1][1], acc[mi][nj1][2], acc[mi][nj1][3],
                             alo[mi][0], alo[mi][1], alo[mi][2], alo[mi][3], bh[2], bh[3]);
                }
            }
        }
        __syncthreads();
    }

    // epilogue: relu + store
    #pragma unroll
    for (int mi = 0; mi < 2; mi++) {
        int rA = row0 + warpM * 32 + mi * 16 + qr;
        int rB = rA + 8;
        #pragma unroll
        for (int nj = 0; nj < 8; nj++) {
            int col = warpN * 64 + nj * 8 + qc * 2;
            if (rA < N_NODES) {
                float2 o;
                o.x = fmaxf(acc[mi][nj][0], 0.f);
                o.y = fmaxf(acc[mi][nj][1], 0.f);
                *reinterpret_cast<float2*>(&out[(size_t)rA * D + col]) = o;
            }
            if (rB < N_NODES) {
                float2 o;
                o.x = fmaxf(acc[mi][nj][2], 0.f);
                o.y = fmaxf(acc[mi][nj][3], 0.f);
                *reinterpret_cast<float2*>(&out[(size_t)rB * D + col]) = o;
            }
        }
    }
#undef LOAD_CHUNK
#undef STORE_CHUNK
}

// ---------------------------------------------------------------------------
extern "C" void kernel_launch(void* const* d_in, const int* in_sizes, int n_in,
                              void* d_out, int out_size)
{
    const float* h   = (const float*)d_in[0];
    const float* d   = (const float*)d_in[1];
    const int*   src = (const int*)d_in[2];
    const int*   dst = (const int*)d_in[3];
    const float* W   = (const float*)d_in[4];
    const float* b   = (const float*)d_in[5];
    float* out = (float*)d_out;

    prep_kernel<<<256, 256>>>(W);
    fill_kernel<<<(N_EDGES / 4 + 255) / 256, 256>>>(d, src, dst);
    gather_kernel<<<(N_NODES + 7) / 8, 256>>>(h);
    gemm_relu_kernel<<<(N_NODES + 127) / 128, 256>>>(b, out);
}

// round 10
// speedup vs baseline: 1.7571x; 1.1718x over previous
#include <cuda_runtime.h>
#include <cuda_fp16.h>
#include <cstdint>

#define N_NODES 50000
#define N_EDGES 625000
#define D       128
#define CAP     64          // bucket capacity per node (max degree ~45 expected)

// ---- scratch (__device__ globals; allocation-free requirement) ----
__device__ int2   g_bucket[N_NODES * CAP]; // 25.6 MB
__device__ int    g_cnt[N_NODES];
__device__ __half g_x[N_NODES * D];        // fp16 gathered node features
__device__ __half g_wt[D * D];             // W transposed fp16: [k][n]

// ---------------------------------------------------------------------------
// 1) prep: zero cnt + transpose W to fp16
// ---------------------------------------------------------------------------
__global__ void prep_kernel(const float* __restrict__ W) {
    int i = blockIdx.x * blockDim.x + threadIdx.x;
    int stride = gridDim.x * blockDim.x;
    for (int idx = i; idx < N_NODES; idx += stride) g_cnt[idx] = 0;
    for (int idx = i; idx < D * D; idx += stride) {
        int n = idx / D, k = idx % D;        // W row-major [n][k]
        g_wt[k * D + n] = __float2half_rn(W[idx]);
    }
}

// ---------------------------------------------------------------------------
// 2) fill buckets: 4 edges per thread (vectorized index loads)
// ---------------------------------------------------------------------------
__global__ void __launch_bounds__(256) fill_kernel(
    const float* __restrict__ d, const int* __restrict__ src,
    const int* __restrict__ dst)
{
    int i = blockIdx.x * blockDim.x + threadIdx.x;
    if (i * 4 >= N_EDGES) return;
    int4   s4 = __ldg(reinterpret_cast<const int4*>(src) + i);
    int4   t4 = __ldg(reinterpret_cast<const int4*>(dst) + i);
    float4 d4 = __ldg(reinterpret_cast<const float4*>(d) + i);

    int p;
    p = atomicAdd(&g_cnt[t4.x], 1);
    if (p < CAP) g_bucket[t4.x * CAP + p] = make_int2(s4.x, __float_as_int(1.0f - d4.x));
    p = atomicAdd(&g_cnt[t4.y], 1);
    if (p < CAP) g_bucket[t4.y * CAP + p] = make_int2(s4.y, __float_as_int(1.0f - d4.y));
    p = atomicAdd(&g_cnt[t4.z], 1);
    if (p < CAP) g_bucket[t4.z * CAP + p] = make_int2(s4.z, __float_as_int(1.0f - d4.z));
    p = atomicAdd(&g_cnt[t4.w], 1);
    if (p < CAP) g_bucket[t4.w * CAP + p] = make_int2(s4.w, __float_as_int(1.0f - d4.w));
}

// ---------------------------------------------------------------------------
// 3) gather: one warp per node; x[v] = sum w_e h[src_e] + max(deg,1) h[v]
//    fp32 accumulate, fp16 output
// ---------------------------------------------------------------------------
__global__ void __launch_bounds__(256) gather_kernel(const float* __restrict__ h) {
    int v = blockIdx.x * (blockDim.x >> 5) + (threadIdx.x >> 5);
    if (v >= N_NODES) return;
    int lane = threadIdx.x & 31;

    int deg = g_cnt[v];
    int cap = min(deg, CAP);
    const float4* h4 = reinterpret_cast<const float4*>(h);
    float4 acc = make_float4(0.f, 0.f, 0.f, 0.f);

    for (int base = 0; base < cap; base += 32) {
        int idx = base + lane;
        int2 ent = make_int2(0, 0);
        if (idx < cap) ent = __ldg(&g_bucket[v * CAP + idx]);
        int cnt = min(32, cap - base);
        #pragma unroll 4
        for (int j = 0; j < cnt; j++) {
            int   sj = __shfl_sync(0xffffffffu, ent.x, j);
            float wj = __int_as_float(__shfl_sync(0xffffffffu, ent.y, j));
            float4 hv = __ldg(&h4[(size_t)sj * 32 + lane]);
            acc.x = fmaf(wj, hv.x, acc.x);
            acc.y = fmaf(wj, hv.y, acc.y);
            acc.z = fmaf(wj, hv.z, acc.z);
            acc.w = fmaf(wj, hv.w, acc.w);
        }
    }

    float degf = fmaxf((float)deg, 1.0f);
    float4 hv = __ldg(&h4[(size_t)v * 32 + lane]);
    __half2 a = __floats2half2_rn(fmaf(degf, hv.x, acc.x), fmaf(degf, hv.y, acc.y));
    __half2 c = __floats2half2_rn(fmaf(degf, hv.z, acc.z), fmaf(degf, hv.w, acc.w));
    uint2 u;
    u.x = *reinterpret_cast<unsigned*>(&a);
    u.y = *reinterpret_cast<unsigned*>(&c);
    *reinterpret_cast<uint2*>(&g_x[(size_t)v * D + lane * 4]) = u;
}

// ---------------------------------------------------------------------------
// 4) GEMM + bias + ReLU: single-shot K=128, fp16 mma.sync m16n8k16.
//    out = relu(x @ Wt + b)
//    256 thr / 8 warps; block tile 128M x 128N; warp 32M x 64N.
//    X tile (128x128 fp16) + full W (128x128 fp16) resident in dynamic smem;
//    ONE barrier, then 8 barrier-free k-steps.
// ---------------------------------------------------------------------------
#define SLD 136       // fp16 elems per smem row (128 + 8 pad) -> ldmatrix conflict-free
#define GEMM_SMEM (2 * 128 * SLD * (int)sizeof(__half))   // 69632 B

__device__ __forceinline__ void ldsm4(unsigned& r0, unsigned& r1, unsigned& r2, unsigned& r3,
                                      const __half* p) {
    unsigned a = (unsigned)__cvta_generic_to_shared(p);
    asm volatile("ldmatrix.sync.aligned.m8n8.x4.shared.b16 {%0,%1,%2,%3}, [%4];"
                 : "=r"(r0), "=r"(r1), "=r"(r2), "=r"(r3) : "r"(a));
}
__device__ __forceinline__ void ldsm4t(unsigned& r0, unsigned& r1, unsigned& r2, unsigned& r3,
                                       const __half* p) {
    unsigned a = (unsigned)__cvta_generic_to_shared(p);
    asm volatile("ldmatrix.sync.aligned.m8n8.x4.trans.shared.b16 {%0,%1,%2,%3}, [%4];"
                 : "=r"(r0), "=r"(r1), "=r"(r2), "=r"(r3) : "r"(a));
}
__device__ __forceinline__ void mma_fp16(
    float& c0, float& c1, float& c2, float& c3,
    unsigned a0, unsigned a1, unsigned a2, unsigned a3,
    unsigned b0, unsigned b1)
{
    asm volatile(
        "mma.sync.aligned.m16n8k16.row.col.f32.f16.f16.f32 "
        "{%0,%1,%2,%3}, {%4,%5,%6,%7}, {%8,%9}, {%0,%1,%2,%3};"
        : "+f"(c0), "+f"(c1), "+f"(c2), "+f"(c3)
        : "r"(a0), "r"(a1), "r"(a2), "r"(a3), "r"(b0), "r"(b1));
}

__global__ void __launch_bounds__(256, 2) gemm_relu_kernel(
    const float* __restrict__ b, float* __restrict__ out)
{
    extern __shared__ __half smem[];
    __half* Xs = smem;                 // 128 x SLD
    __half* Ws = smem + 128 * SLD;     // 128 x SLD

    const int tid  = threadIdx.x;
    const int wid  = tid >> 5;
    const int lane = tid & 31;
    const int warpM = wid & 3;
    const int warpN = wid >> 2;
    const int row0 = blockIdx.x * 128;
    const int qr = lane >> 2;
    const int qc = lane & 3;

    // ---- stage X tile and W (whole K) ----
    // 2 threads per row; each thread copies 64 fp16 = 8 x uint4
    const int xm = tid >> 1;
    const int xseg = (tid & 1) * 64;
    const int grow = row0 + xm;
    const bool rowok = grow < N_NODES;
    {
        const uint4 zz = make_uint4(0, 0, 0, 0);
        const uint4* gx = reinterpret_cast<const uint4*>(&g_x[(size_t)(rowok ? grow : 0) * D + xseg]);
        const uint4* gw = reinterpret_cast<const uint4*>(&g_wt[xm * D + xseg]);
        #pragma unroll
        for (int q = 0; q < 8; q++) {
            uint4 vx = rowok ? __ldg(&gx[q]) : zz;
            *reinterpret_cast<uint4*>(&Xs[xm * SLD + xseg + q * 8]) = vx;
            *reinterpret_cast<uint4*>(&Ws[xm * SLD + xseg + q * 8]) = __ldg(&gw[q]);
        }
    }

    // accumulators, init with bias
    float acc[2][8][4];
    #pragma unroll
    for (int nj = 0; nj < 8; nj++) {
        int col = warpN * 64 + nj * 8 + qc * 2;
        float b0 = __ldg(&b[col]);
        float b1 = __ldg(&b[col + 1]);
        #pragma unroll
        for (int mi = 0; mi < 2; mi++) {
            acc[mi][nj][0] = b0; acc[mi][nj][1] = b1;
            acc[mi][nj][2] = b0; acc[mi][nj][3] = b1;
        }
    }

    const int lrow = (lane & 7) + ((lane >> 3) & 1) * 8;
    const int lk8  = (lane >> 4) * 8;

    __syncthreads();   // the only barrier

    #pragma unroll
    for (int ks = 0; ks < 8; ks++) {
        const int k0 = ks * 16;
        unsigned a[2][4];
        #pragma unroll
        for (int mi = 0; mi < 2; mi++)
            ldsm4(a[mi][0], a[mi][1], a[mi][2], a[mi][3],
                  &Xs[(warpM * 32 + mi * 16 + lrow) * SLD + k0 + lk8]);
        #pragma unroll
        for (int njp = 0; njp < 4; njp++) {
            const int n0 = warpN * 64 + njp * 16;
            unsigned bf[4];
            ldsm4t(bf[0], bf[1], bf[2], bf[3], &Ws[(k0 + lrow) * SLD + n0 + lk8]);
            const int nj0 = njp * 2, nj1 = njp * 2 + 1;
            #pragma unroll
            for (int mi = 0; mi < 2; mi++) {
                mma_fp16(acc[mi][nj0][0], acc[mi][nj0][1], acc[mi][nj0][2], acc[mi][nj0][3],
                         a[mi][0], a[mi][1], a[mi][2], a[mi][3], bf[0], bf[1]);
                mma_fp16(acc[mi][nj1][0], acc[mi][nj1][1], acc[mi][nj1][2], acc[mi][nj1][3],
                         a[mi][0], a[mi][1], a[mi][2], a[mi][3], bf[2], bf[3]);
            }
        }
    }

    // epilogue: relu + store
    #pragma unroll
    for (int mi = 0; mi < 2; mi++) {
        int rA = row0 + warpM * 32 + mi * 16 + qr;
        int rB = rA + 8;
        #pragma unroll
        for (int nj = 0; nj < 8; nj++) {
            int col = warpN * 64 + nj * 8 + qc * 2;
            if (rA < N_NODES) {
                float2 o;
                o.x = fmaxf(acc[mi][nj][0], 0.f);
                o.y = fmaxf(acc[mi][nj][1], 0.f);
                *reinterpret_cast<float2*>(&out[(size_t)rA * D + col]) = o;
            }
            if (rB < N_NODES) {
                float2 o;
                o.x = fmaxf(acc[mi][nj][2], 0.f);
                o.y = fmaxf(acc[mi][nj][3], 0.f);
                *reinterpret_cast<float2*>(&out[(size_t)rB * D + col]) = o;
            }
        }
    }
}

// ---------------------------------------------------------------------------
extern "C" void kernel_launch(void* const* d_in, const int* in_sizes, int n_in,
                              void* d_out, int out_size)
{
    const float* h   = (const float*)d_in[0];
    const float* d   = (const float*)d_in[1];
    const int*   src = (const int*)d_in[2];
    const int*   dst = (const int*)d_in[3];
    const float* W   = (const float*)d_in[4];
    const float* b   = (const float*)d_in[5];
    float* out = (float*)d_out;

    // dynamic smem opt-in (host attribute set; idempotent, not a stream op)
    cudaFuncSetAttribute(gemm_relu_kernel,
                         cudaFuncAttributeMaxDynamicSharedMemorySize, GEMM_SMEM);

    prep_kernel<<<256, 256>>>(W);
    fill_kernel<<<(N_EDGES / 4 + 255) / 256, 256>>>(d, src, dst);
    gather_kernel<<<(N_NODES + 7) / 8, 256>>>(h);
    gemm_relu_kernel<<<(N_NODES + 127) / 128, 256, GEMM_SMEM>>>(b, out);
}